// round 1
// baseline (speedup 1.0000x reference)
#include <cuda_runtime.h>
#include <math.h>

#define BROWS 8192
#define HIDK  1024
#define HH    64
#define QQ    99
#define NI    640
#define NOUT  (HH*QQ)   // 6336

// Intermediate scratch (allocation-free rule: __device__ globals)
__device__ float g_med[BROWS * HH];   // 2 MB
__device__ float g_inc[BROWS * NI];   // 20 MB

#define BM 128
#define BN 64
#define BK 32
#define ASST 132   // padded k-major A stage (keeps float4-compat alignment, kills conflicts)
#define BSST 68    // padded B stage
#define NKT (HIDK / BK)   // 32

__device__ __forceinline__ unsigned f2tf(float f) {
    unsigned u;
    asm("cvt.rna.tf32.f32 %0, %1;" : "=r"(u) : "f"(f));
    return u;
}

__device__ __forceinline__ void mma8(float c[4], const unsigned a[4], const unsigned b[2]) {
    asm volatile(
        "mma.sync.aligned.m16n8k8.row.col.f32.tf32.tf32.f32 "
        "{%0,%1,%2,%3}, {%4,%5,%6,%7}, {%8,%9}, {%0,%1,%2,%3};\n"
        : "+f"(c[0]), "+f"(c[1]), "+f"(c[2]), "+f"(c[3])
        : "r"(a[0]), "r"(a[1]), "r"(a[2]), "r"(a[3]), "r"(b[0]), "r"(b[1]));
}

__device__ __forceinline__ float softplusf(float v) {
    // matches jax.nn.softplus = max(x,0) + log1p(exp(-|x|))
    return fmaxf(v, 0.f) + log1pf(expf(-fabsf(v)));
}

// ---------------------------------------------------------------------------
// Kernel 1: fused GEMM  C = x @ [Wm | Wi] + bias, softplus on the Wi part.
// Block tile 128x64, BK=32, 8 warps, tf32 mma.sync m16n8k8, warp tile 32x32.
// blockIdx.y == 0 -> median (Wm, 64 cols); 1..10 -> inc block of 64 Wi cols.
// ---------------------------------------------------------------------------
__global__ __launch_bounds__(256) void gemm_kernel(
    const float* __restrict__ x,
    const float* __restrict__ Wm, const float* __restrict__ bm,
    const float* __restrict__ Wi, const float* __restrict__ bi)
{
    __shared__ float As[BK * ASST];
    __shared__ float Bs[BK * BSST];

    const int tid = threadIdx.x;
    const int by  = blockIdx.y;
    const int m0  = blockIdx.x * BM;

    const float* Bp; int ldb;
    if (by == 0) { Bp = Wm; ldb = HH; } else { Bp = Wi + (by - 1) * BN; ldb = NI; }

    const int wid = tid >> 5, lane = tid & 31;
    const int g = lane >> 2, tg = lane & 3;
    const int wm = (wid & 3) * 32;
    const int wn = (wid >> 2) * 32;

    float acc[2][4][4];
    #pragma unroll
    for (int mt = 0; mt < 2; mt++)
      #pragma unroll
      for (int nt = 0; nt < 4; nt++)
        #pragma unroll
        for (int i = 0; i < 4; i++) acc[mt][nt][i] = 0.f;

    // per-thread staging coordinates
    int arow[4], acol[4];
    #pragma unroll
    for (int i = 0; i < 4; i++) { int idx = tid + i*256; arow[i] = idx >> 3; acol[i] = (idx & 7) * 4; }
    int bkk[2], bnn[2];
    #pragma unroll
    for (int i = 0; i < 2; i++) { int idx = tid + i*256; bkk[i] = idx >> 4; bnn[i] = (idx & 15) * 4; }

    float4 aR[4], bR[2];
    // prologue: load k-tile 0 into registers
    {
        const float* xb = x + (size_t)m0 * HIDK;
        #pragma unroll
        for (int i = 0; i < 4; i++) aR[i] = *(const float4*)(xb + (size_t)arow[i]*HIDK + acol[i]);
        #pragma unroll
        for (int i = 0; i < 2; i++) bR[i] = *(const float4*)(Bp + (size_t)bkk[i]*ldb + bnn[i]);
    }

    for (int kt = 0; kt < NKT; kt++) {
        // stage registers -> smem (A transposed to k-major)
        #pragma unroll
        for (int i = 0; i < 4; i++) {
            As[(acol[i]+0)*ASST + arow[i]] = aR[i].x;
            As[(acol[i]+1)*ASST + arow[i]] = aR[i].y;
            As[(acol[i]+2)*ASST + arow[i]] = aR[i].z;
            As[(acol[i]+3)*ASST + arow[i]] = aR[i].w;
        }
        #pragma unroll
        for (int i = 0; i < 2; i++) *(float4*)&Bs[bkk[i]*BSST + bnn[i]] = bR[i];
        __syncthreads();

        // overlap: issue next tile's global loads while computing this one
        if (kt + 1 < NKT) {
            const float* xb = x + (size_t)m0 * HIDK + (kt+1)*BK;
            #pragma unroll
            for (int i = 0; i < 4; i++) aR[i] = *(const float4*)(xb + (size_t)arow[i]*HIDK + acol[i]);
            const float* bb = Bp + (size_t)(kt+1)*BK*ldb;
            #pragma unroll
            for (int i = 0; i < 2; i++) bR[i] = *(const float4*)(bb + (size_t)bkk[i]*ldb + bnn[i]);
        }

        #pragma unroll
        for (int ks = 0; ks < 4; ks++) {
            const int kb = ks * 8;
            unsigned af[2][4], bf[4][2];
            #pragma unroll
            for (int mt = 0; mt < 2; mt++) {
                const int rb = wm + mt*16 + g;
                af[mt][0] = f2tf(As[(kb+tg  )*ASST + rb    ]);
                af[mt][1] = f2tf(As[(kb+tg  )*ASST + rb + 8]);
                af[mt][2] = f2tf(As[(kb+tg+4)*ASST + rb    ]);
                af[mt][3] = f2tf(As[(kb+tg+4)*ASST + rb + 8]);
            }
            #pragma unroll
            for (int nt = 0; nt < 4; nt++) {
                const int cb = wn + nt*8 + g;
                bf[nt][0] = f2tf(Bs[(kb+tg  )*BSST + cb]);
                bf[nt][1] = f2tf(Bs[(kb+tg+4)*BSST + cb]);
            }
            #pragma unroll
            for (int mt = 0; mt < 2; mt++)
              #pragma unroll
              for (int nt = 0; nt < 4; nt++)
                mma8(acc[mt][nt], af[mt], bf[nt]);
        }
        __syncthreads();
    }

    // epilogue: bias (+ softplus for inc part), float2 stores
    #pragma unroll
    for (int mt = 0; mt < 2; mt++) {
      #pragma unroll
      for (int nt = 0; nt < 4; nt++) {
        #pragma unroll
        for (int hf = 0; hf < 2; hf++) {
            const int row = m0 + wm + mt*16 + g + hf*8;
            const int col = wn + nt*8 + tg*2;
            float v0 = acc[mt][nt][hf*2 + 0];
            float v1 = acc[mt][nt][hf*2 + 1];
            if (by == 0) {
                v0 += bm[col]; v1 += bm[col+1];
                *(float2*)&g_med[(size_t)row*HH + col] = make_float2(v0, v1);
            } else {
                const int nc = (by-1)*BN + col;
                v0 = softplusf(v0 + bi[nc]);
                v1 = softplusf(v1 + bi[nc+1]);
                *(float2*)&g_inc[(size_t)row*NI + nc] = make_float2(v0, v1);
            }
        }
      }
    }
}

// ---------------------------------------------------------------------------
// Kernel 2: per-row quantile expansion. One block per batch row.
//   rank[q]  = stable rank of quantiles[b,q]
//   m_idx    = rank of the quantile minimizing |q - 0.5| (first-in-sorted tie)
//   cum0(s)  = (s/10)*P10 + prefix[s%10]   (pattern is 10-periodic)
//   out[b,h,q] = median[b,h] + sign(rank[q]-m_idx) * cum0(|rank[q]-m_idx|)
// ---------------------------------------------------------------------------
__global__ __launch_bounds__(256) void out_kernel(const float* __restrict__ quant,
                                                  float* __restrict__ out)
{
    __shared__ float qv[QQ], key_s[QQ], sgn_s[QQ], div_s[QQ];
    __shared__ int   rank_s[QQ], mod_s[QQ];
    __shared__ float ph[HH][12];   // prefix[0..10] per head
    __shared__ float med_s[HH];
    __shared__ int   midx_s;

    const int b = blockIdx.x, tid = threadIdx.x;

    if (tid < QQ) qv[tid] = quant[(size_t)b*QQ + tid];
    __syncthreads();

    if (tid < QQ) {
        const float v = qv[tid];
        int r = 0;
        for (int j = 0; j < QQ; j++) {
            const float u = qv[j];
            r += (u < v) || (u == v && j < tid);   // stable argsort rank
        }
        rank_s[tid] = r;
        key_s[tid]  = fabsf(v - 0.5f);
    } else if (tid >= 128 && tid < 192) {
        const int h = tid - 128;
        const float* ip = g_inc + (size_t)b*NI + h*10;
        float s = 0.f;
        ph[h][0] = 0.f;
        #pragma unroll
        for (int j = 0; j < 10; j++) { s += ip[j]; ph[h][j+1] = s; }
    } else if (tid >= 192) {
        med_s[tid - 192] = g_med[(size_t)b*HH + (tid - 192)];
    }
    __syncthreads();

    if (tid == 0) {
        float bk = key_s[0]; int br = rank_s[0];
        for (int j = 1; j < QQ; j++) {
            const float k = key_s[j]; const int r = rank_s[j];
            if (k < bk || (k == bk && r < br)) { bk = k; br = r; }
        }
        midx_s = br;
    }
    __syncthreads();

    if (tid < QQ) {
        const int d  = rank_s[tid] - midx_s;
        const int st = d < 0 ? -d : d;
        sgn_s[tid] = (float)((d > 0) - (d < 0));
        div_s[tid] = (float)(st / 10);
        mod_s[tid] = st % 10;
    }
    __syncthreads();

    float* ob = out + (size_t)b * NOUT;
    for (int i = tid; i < NOUT; i += 256) {
        const int h = i / QQ;
        const int q = i - h * QQ;
        ob[i] = fmaf(sgn_s[q], fmaf(div_s[q], ph[h][10], ph[h][mod_s[q]]), med_s[h]);
    }
}

extern "C" void kernel_launch(void* const* d_in, const int* in_sizes, int n_in,
                              void* d_out, int out_size) {
    const float* x     = (const float*)d_in[0];
    const float* quant = (const float*)d_in[1];
    const float* Wm    = (const float*)d_in[2];
    const float* bm    = (const float*)d_in[3];
    const float* Wi    = (const float*)d_in[4];
    const float* bi    = (const float*)d_in[5];
    float* out = (float*)d_out;

    dim3 grid(BROWS / BM, 11);   // 64 x 11 (col-block 0 = Wm, 1..10 = Wi)
    gemm_kernel<<<grid, 256>>>(x, Wm, bm, Wi, bi);
    out_kernel<<<BROWS, 256>>>(quant, out);
}

// round 5
// speedup vs baseline: 1.9468x; 1.9468x over previous
#include <cuda_runtime.h>
#include <cuda_bf16.h>
#include <math.h>
#include <stdint.h>

#define BROWS 8192
#define HIDK  1024
#define HH    64
#define QQ    99
#define NI    640
#define NTOT  704          // 64 + 640 output cols
#define NOUT  (HH*QQ)      // 6336

// ---------------- scratch (allocation-free rule: __device__ globals) -------
__device__ float          g_med[BROWS * HH];      // 2 MB
__device__ float          g_inc[BROWS * NI];      // 20 MB
__device__ __nv_bfloat16  g_xb [BROWS * HIDK];    // 16 MB  x in bf16
__device__ __nv_bfloat16  g_wt [NTOT  * HIDK];    // 1.4 MB [Wm|Wi]^T, n-major rows

// ---------------- helpers ---------------------------------------------------
__device__ __forceinline__ uint32_t smem_u32(const void* p) {
    uint32_t a;
    asm("{ .reg .u64 t; cvta.to.shared.u64 t, %1; cvt.u32.u64 %0, t; }" : "=r"(a) : "l"(p));
    return a;
}
__device__ __forceinline__ void cp_async16(uint32_t saddr, const void* gptr) {
    asm volatile("cp.async.cg.shared.global [%0], [%1], 16;" :: "r"(saddr), "l"(gptr));
}
__device__ __forceinline__ void cp_commit() { asm volatile("cp.async.commit_group;"); }
template <int N>
__device__ __forceinline__ void cp_wait() { asm volatile("cp.async.wait_group %0;" :: "n"(N)); }

__device__ __forceinline__ void ldmx4(uint32_t& r0, uint32_t& r1, uint32_t& r2, uint32_t& r3,
                                      uint32_t addr) {
    asm volatile("ldmatrix.sync.aligned.m8n8.x4.shared.b16 {%0,%1,%2,%3}, [%4];"
                 : "=r"(r0), "=r"(r1), "=r"(r2), "=r"(r3) : "r"(addr));
}
__device__ __forceinline__ void mma16(float c[4], const uint32_t a[4], const uint32_t b[2]) {
    asm volatile(
        "mma.sync.aligned.m16n8k16.row.col.f32.bf16.bf16.f32 "
        "{%0,%1,%2,%3}, {%4,%5,%6,%7}, {%8,%9}, {%0,%1,%2,%3};"
        : "+f"(c[0]), "+f"(c[1]), "+f"(c[2]), "+f"(c[3])
        : "r"(a[0]), "r"(a[1]), "r"(a[2]), "r"(a[3]), "r"(b[0]), "r"(b[1]));
}
__device__ __forceinline__ float softplusf(float v) {
    return fmaxf(v, 0.f) + log1pf(expf(-fabsf(v)));
}

// ---------------------------------------------------------------------------
// Prep: x (f32) -> g_xb (bf16)
// ---------------------------------------------------------------------------
__global__ __launch_bounds__(256) void cvt_x_kernel(const float* __restrict__ x) {
    const int i = blockIdx.x * 256 + threadIdx.x;          // float4 index
    float4 v = ((const float4*)x)[i];
    __nv_bfloat162 p0 = __floats2bfloat162_rn(v.x, v.y);
    __nv_bfloat162 p1 = __floats2bfloat162_rn(v.z, v.w);
    uint2 u;
    u.x = *(uint32_t*)&p0;
    u.y = *(uint32_t*)&p1;
    ((uint2*)g_xb)[i] = u;
}

// Prep: g_wt[n][k] = (n < 64 ? Wm[k][n] : Wi[k][n-64]) as bf16  (one block per n)
__global__ __launch_bounds__(256) void cvt_w_kernel(const float* __restrict__ Wm,
                                                    const float* __restrict__ Wi) {
    const int n = blockIdx.x;
    const float* src;
    int ld, c;
    if (n < HH) { src = Wm; ld = HH; c = n; } else { src = Wi; ld = NI; c = n - HH; }
    __nv_bfloat16* dst = g_wt + (size_t)n * HIDK;
    #pragma unroll
    for (int it = 0; it < 4; it++) {
        const int k = threadIdx.x + it * 256;
        dst[k] = __float2bfloat16(src[(size_t)k * ld + c]);
    }
}

// ---------------------------------------------------------------------------
// Kernel 1: bf16 mma.sync m16n8k16 GEMM. Tile 128x64, BK=64, cp.async 2-stage.
// 8 warps as 4(m) x 2(n); warp tile 32x32. grid (64, 11):
// blockIdx.y==0 -> median cols (Wm), 1..10 -> 64-col block of Wi.
// ---------------------------------------------------------------------------
#define BM 128
#define BN 64
#define BK 64
#define ASTR 72                       // bf16 elems per smem row (+16B pad: conflict-free ldmatrix)
#define ABYTES (BM * ASTR * 2)        // 18432
#define BBYTES (BN * ASTR * 2)        // 9216
#define STAGE  (ABYTES + BBYTES)      // 27648
#define SMEMSZ (2 * STAGE)            // 55296
#define NKC (HIDK / BK)               // 16

__global__ __launch_bounds__(256) void gemm_kernel(const float* __restrict__ bm,
                                                   const float* __restrict__ bi) {
    extern __shared__ char sm[];
    const uint32_t smb = smem_u32(sm);

    const int tid  = threadIdx.x;
    const int wid  = tid >> 5, lane = tid & 31;
    const int m0   = blockIdx.x * BM;
    const int by   = blockIdx.y;
    const int n0   = by * BN;

    const int wm = (wid & 3) * 32;        // warp m offset in tile
    const int wn = (wid >> 2) * 32;       // warp n offset in tile

    const __nv_bfloat16* Abase = g_xb + (size_t)m0 * HIDK;
    const __nv_bfloat16* Bbase = g_wt + (size_t)n0 * HIDK;

    // cp.async staging coords (16B = 8 bf16 per op)
    const int ar = tid >> 3, ac = (tid & 7) * 8;          // +128 rows per rep (4 reps)
    const int br = tid >> 3, bc = (tid & 7) * 8;          // rows 0..31 (+32 per rep, 2 reps)

    float acc[2][4][4];
    #pragma unroll
    for (int mt = 0; mt < 2; mt++)
      #pragma unroll
      for (int nt = 0; nt < 4; nt++)
        #pragma unroll
        for (int i = 0; i < 4; i++) acc[mt][nt][i] = 0.f;

    // ldmatrix per-lane addresses (byte offsets within stage, A/B parts)
    const int quad = lane >> 3, rin = lane & 7;
    // A 16x16 tile at (mrow0, k0): lanes0-7 m0-7 k0, 8-15 m8-15 k0, 16-23 m0-7 k8, 24-31 m8-15 k8
    const int a_row = wm + rin + (quad & 1) * 8;          // + mt*16
    const int a_kof = (quad >> 1) * 8;                    // + ks*16
    // B pair (16n x 16k): lanes0-7 n0-7 k0, 8-15 n0-7 k8, 16-23 n8-15 k0, 24-31 n8-15 k8
    const int b_row = wn + rin + (quad >> 1) * 8;         // + p*16
    const int b_kof = (quad & 1) * 8;                     // + ks*16

    // prologue: stage chunk 0
    {
        #pragma unroll
        for (int i = 0; i < 4; i++)
            cp_async16(smb + (uint32_t)((ar + i * 32) * ASTR + ac) * 2,
                       Abase + (size_t)(ar + i * 32) * HIDK + ac);
        #pragma unroll
        for (int i = 0; i < 2; i++)
            cp_async16(smb + ABYTES + (uint32_t)((br + i * 32) * ASTR + bc) * 2,
                       Bbase + (size_t)(br + i * 32) * HIDK + bc);
        cp_commit();
    }

    for (int kc = 0; kc < NKC; kc++) {
        const int buf = kc & 1;
        const uint32_t sa = smb + (buf ? STAGE : 0);
        const uint32_t sbB = sa + ABYTES;

        if (kc + 1 < NKC) {                                 // prefetch next chunk
            const int nb = 1 - buf;
            const uint32_t pa = smb + (nb ? STAGE : 0);
            const __nv_bfloat16* Ag = Abase + (size_t)(kc + 1) * BK;
            const __nv_bfloat16* Bg = Bbase + (size_t)(kc + 1) * BK;
            #pragma unroll
            for (int i = 0; i < 4; i++)
                cp_async16(pa + (uint32_t)((ar + i * 32) * ASTR + ac) * 2,
                           Ag + (size_t)(ar + i * 32) * HIDK + ac);
            #pragma unroll
            for (int i = 0; i < 2; i++)
                cp_async16(pa + ABYTES + (uint32_t)((br + i * 32) * ASTR + bc) * 2,
                           Bg + (size_t)(br + i * 32) * HIDK + bc);
            cp_commit();
            cp_wait<1>();
        } else {
            cp_wait<0>();
        }
        __syncthreads();

        #pragma unroll
        for (int ks = 0; ks < 4; ks++) {
            uint32_t af[2][4], bf[2][4];
            #pragma unroll
            for (int mt = 0; mt < 2; mt++)
                ldmx4(af[mt][0], af[mt][1], af[mt][2], af[mt][3],
                      sa + (uint32_t)((a_row + mt * 16) * ASTR + ks * 16 + a_kof) * 2);
            #pragma unroll
            for (int p = 0; p < 2; p++)
                ldmx4(bf[p][0], bf[p][1], bf[p][2], bf[p][3],
                      sbB + (uint32_t)((b_row + p * 16) * ASTR + ks * 16 + b_kof) * 2);
            #pragma unroll
            for (int mt = 0; mt < 2; mt++)
              #pragma unroll
              for (int nt = 0; nt < 4; nt++)
                mma16(acc[mt][nt], af[mt], &bf[nt >> 1][(nt & 1) * 2]);
        }
        __syncthreads();   // all warps done with buf before it is re-staged
    }

    // epilogue: bias (+ softplus for inc part), float2 stores
    const int g = lane >> 2, tg = lane & 3;
    #pragma unroll
    for (int mt = 0; mt < 2; mt++) {
      #pragma unroll
      for (int nt = 0; nt < 4; nt++) {
        #pragma unroll
        for (int hf = 0; hf < 2; hf++) {
            const int row = m0 + wm + mt * 16 + g + hf * 8;
            const int col = wn + nt * 8 + tg * 2;
            float v0 = acc[mt][nt][hf * 2 + 0];
            float v1 = acc[mt][nt][hf * 2 + 1];
            if (by == 0) {
                v0 += __ldg(bm + col); v1 += __ldg(bm + col + 1);
                *(float2*)&g_med[(size_t)row * HH + col] = make_float2(v0, v1);
            } else {
                const int nc = (by - 1) * BN + col;
                v0 = softplusf(v0 + __ldg(bi + nc));
                v1 = softplusf(v1 + __ldg(bi + nc + 1));
                *(float2*)&g_inc[(size_t)row * NI + nc] = make_float2(v0, v1);
            }
        }
      }
    }
}

// ---------------------------------------------------------------------------
// Kernel 2: per-row quantile expansion. One block per batch row.
//   rank[q] = stable rank; m_idx = rank of argmin |q-0.5| (first-in-sorted tie)
//   cum0(s) = (s/10)*P10 + prefix[s%10]  (pattern is 10-periodic)
//   out[b,h,q] = med[h] + sgn_q*prefix[h][mod_q] + (sgn_q*div_q)*P10[h]
// ph[h][0..10] = prefix, ph[h][11] = median
// ---------------------------------------------------------------------------
__global__ __launch_bounds__(256) void out_kernel(const float* __restrict__ quant,
                                                  float* __restrict__ out) {
    __shared__ float qv[QQ], key_s[QQ];
    __shared__ int   rank_s[QQ];
    __shared__ float sgn_s[QQ], c1_s[QQ];
    __shared__ int   mod_s[QQ];
    __shared__ float ph[HH][12];
    __shared__ int   midx_s;

    const int b = blockIdx.x, tid = threadIdx.x;

    if (tid < QQ) qv[tid] = quant[(size_t)b * QQ + tid];
    __syncthreads();

    if (tid < QQ) {
        const float v = qv[tid];
        int r = 0;
        #pragma unroll 4
        for (int j = 0; j < QQ; j++) {
            const float u = qv[j];
            r += (u < v) || (u == v && j < tid);          // stable argsort rank
        }
        rank_s[tid] = r;
        key_s[tid]  = fabsf(v - 0.5f);
    } else if (tid >= 128 && tid < 192) {
        const int h = tid - 128;
        const float* ip = g_inc + (size_t)b * NI + h * 10;
        float s = 0.f;
        ph[h][0] = 0.f;
        #pragma unroll
        for (int j = 0; j < 10; j++) { s += ip[j]; ph[h][j + 1] = s; }
    } else if (tid >= 192) {
        ph[tid - 192][11] = g_med[(size_t)b * HH + (tid - 192)];
    }
    __syncthreads();

    if (tid == 0) {
        float bk = key_s[0]; int br = rank_s[0];
        for (int j = 1; j < QQ; j++) {
            const float k = key_s[j]; const int r = rank_s[j];
            if (k < bk || (k == bk && r < br)) { bk = k; br = r; }
        }
        midx_s = br;
    }
    __syncthreads();

    if (tid < QQ) {
        const int d  = rank_s[tid] - midx_s;
        const int st = d < 0 ? -d : d;
        const float sg = (float)((d > 0) - (d < 0));
        sgn_s[tid] = sg;
        c1_s[tid]  = sg * (float)(st / 10);
        mod_s[tid] = st % 10;
    }
    __syncthreads();

    if (tid < 198) {
        const int hl = tid / 99;                 // one div total, loop-invariant
        const int q0 = tid - hl * 99;
        const float sg = sgn_s[q0];
        const float c1 = c1_s[q0];
        const int   md = mod_s[q0];
        float* ob = out + (size_t)b * NOUT + hl * QQ + q0;
        #pragma unroll
        for (int hb = 0; hb < HH; hb += 2) {
            const int h = hb + hl;
            const float pv  = ph[h][md];
            const float p10 = ph[h][10];
            const float mv  = ph[h][11];
            ob[hb * QQ] = fmaf(c1, p10, fmaf(sg, pv, mv));
        }
    }
}

// ---------------------------------------------------------------------------
extern "C" void kernel_launch(void* const* d_in, const int* in_sizes, int n_in,
                              void* d_out, int out_size) {
    const float* x     = (const float*)d_in[0];
    const float* quant = (const float*)d_in[1];
    const float* Wm    = (const float*)d_in[2];
    const float* bm    = (const float*)d_in[3];
    const float* Wi    = (const float*)d_in[4];
    const float* bi    = (const float*)d_in[5];
    float* out = (float*)d_out;

    cudaFuncSetAttribute(gemm_kernel, cudaFuncAttributeMaxDynamicSharedMemorySize, SMEMSZ);

    cvt_x_kernel<<<(BROWS * HIDK) / (256 * 4), 256>>>(x);
    cvt_w_kernel<<<NTOT, 256>>>(Wm, Wi);
    gemm_kernel<<<dim3(BROWS / BM, 11), 256, SMEMSZ>>>(bm, bi);
    out_kernel<<<BROWS, 256>>>(quant, out);
}